// round 13
// baseline (speedup 1.0000x reference)
#include <cuda_runtime.h>
#include <cuda_fp16.h>
#include <math.h>

// Problem constants
#define B_      256
#define U_      512
#define T_STEPS 256
#define NTn     8       // n tiles (512 / 64)
#define N_TILE  64
#define NCOMP   128     // compute CTAs (16 m-groups x 8 n-tiles)
#define NRED    8       // reducer CTAs
#define THREADS 256
#define WT_STRIDE 1032  // padded row stride (halfs): conflict-free LDSM
#define ZDEPTH  8

// Packed hidden-state storage: slab(par,col) = [m=16][kk=32][j=4][lane=32] u32
__device__ unsigned int g_statesP[2 * 16 * 16 * 32 * 4 * 32];
// logit partials: [ZDEPTH][NTn][4 warps][B] float2
__device__ float2 g_zpart[ZDEPTH * NTn * 4 * B_];
// per-CTA completed-step counters (8 per m-group), z-ready counters, reducer flags
__device__ int g_flags[NCOMP];
__device__ int g_zflags[NCOMP];
__device__ int g_rflags[NRED];

// ---- smem layout offsets (bytes) ----
#define SM_WT    0                       // 64 x 1032 halves = 132096
#define SM_CV    132096                  // cv stage, 16 KB
#define SM_FR    148480                  // fresh stage, 16 KB
#define SM_PART  164864                  // K-split partials: 8 warps x 32 x 8 fp32 = 8 KB
#define SM_SMALL 173056                  // 448 floats = 1792
#define SM_SX    174848                  // 8192 (reducers cache 32 rows)
#define SM_TOTAL 183040

__device__ __forceinline__ int ld_acquire(const int* p) {
    int v;
    asm volatile("ld.global.acquire.gpu.b32 %0, [%1];" : "=r"(v) : "l"(p) : "memory");
    return v;
}
__device__ __forceinline__ void st_release(int* p, int v) {
    asm volatile("st.global.release.gpu.b32 [%0], %1;" :: "l"(p), "r"(v) : "memory");
}
__device__ __forceinline__ float2 ldg_cg_f2(const float2* p) {
    float2 v;
    asm volatile("ld.global.cg.v2.f32 {%0,%1}, [%2];" : "=f"(v.x), "=f"(v.y) : "l"(p));
    return v;
}
__device__ __forceinline__ void cp_async16(unsigned smem_addr, const void* gptr) {
    asm volatile("cp.async.cg.shared.global [%0], [%1], 16;"
                 :: "r"(smem_addr), "l"(gptr));
}
__device__ __forceinline__ void cp_commit() {
    asm volatile("cp.async.commit_group;");
}
template <int N>
__device__ __forceinline__ void cp_wait() {
    asm volatile("cp.async.wait_group %0;" :: "n"(N) : "memory");
}
__device__ __forceinline__ void bar_sync(int id, int cnt) {
    asm volatile("bar.sync %0, %1;" :: "r"(id), "r"(cnt) : "memory");
}

__device__ __forceinline__ void mma16816(float acc[4],
    unsigned a0, unsigned a1, unsigned a2, unsigned a3,
    unsigned b0, unsigned b1)
{
    asm volatile(
        "mma.sync.aligned.m16n8k16.row.col.f32.f16.f16.f32 "
        "{%0,%1,%2,%3}, {%4,%5,%6,%7}, {%8,%9}, {%0,%1,%2,%3};"
        : "+f"(acc[0]), "+f"(acc[1]), "+f"(acc[2]), "+f"(acc[3])
        : "r"(a0), "r"(a1), "r"(a2), "r"(a3), "r"(b0), "r"(b1));
}

__device__ __forceinline__ unsigned* pslab(int par, int col) {
    return g_statesP + (((par << 4) + col) << 16);   // 65536 u32 per slab
}

// runtime-count half-GEMM via ldmatrix.x4 (A packed [kk][j][lane], B = weights)
__device__ __forceinline__ void gemm_r(unsigned aB, unsigned bB, int nkk, float acc[2][4]) {
#pragma unroll 8
    for (int kk = 0; kk < nkk; ++kk) {
        unsigned a0, a1, a2, a3, b0, b1, b2, b3;
        asm volatile("ldmatrix.sync.aligned.m8n8.x4.shared.b16 {%0,%1,%2,%3}, [%4];"
            : "=r"(a0), "=r"(a1), "=r"(a2), "=r"(a3) : "r"(aB));
        asm volatile("ldmatrix.sync.aligned.m8n8.x4.shared.b16 {%0,%1,%2,%3}, [%4];"
            : "=r"(b0), "=r"(b1), "=r"(b2), "=r"(b3) : "r"(bB));
        mma16816(acc[0], a0, a1, a2, a3, b0, b1);
        mma16816(acc[1], a0, a1, a2, a3, b2, b3);
        aB += 512;
        bB += 32;
    }
}

__device__ __forceinline__ float elu1(float v) {
    return v > 0.f ? v : (__expf(v) - 1.f);
}
__device__ __forceinline__ unsigned packh2(float a, float b) {
    __half2 h = __floats2half2_rn(a, b);
    return *reinterpret_cast<unsigned*>(&h);
}

__global__ void rnn2d_init_kernel() {
    if (threadIdx.x < NCOMP) { g_flags[threadIdx.x] = 0; g_zflags[threadIdx.x] = 0; }
    if (threadIdx.x < NRED)  g_rflags[threadIdx.x] = 0;
}

__global__ void __launch_bounds__(THREADS) rnn2d_main_kernel(
    const int* __restrict__ x,
    const float* __restrict__ Wih, const float* __restrict__ Wiv,
    const float* __restrict__ Wch, const float* __restrict__ bch,
    const float* __restrict__ Wcv, const float* __restrict__ Wout,
    const float* __restrict__ bout, float* __restrict__ out)
{
    extern __shared__ unsigned char smem[];
    __half* Wt   = (__half*)(smem + SM_WT);
    float*  sPart= (float*)(smem + SM_PART);     // [8 warps][32 lanes][8]
    float* sWih  = (float*)(smem + SM_SMALL);
    float* sWiv  = sWih + 128;
    float* sBch  = sWiv + 128;
    float* sWo0  = sBch + 64;
    float* sWo1  = sWo0 + 64;
    unsigned char* sx = (unsigned char*)(smem + SM_SX);

    const int bx  = blockIdx.x;
    const int tid = threadIdx.x;

    if (bx >= NCOMP) {
        // ---------------- reducer CTA (off the critical path) ----------------
        const int mr = bx - NCOMP;                 // rows 32*mr .. 32*mr+31
        for (int i = tid; i < 8192; i += THREADS) {
            int rl = i & 31, cell = i >> 5;
            sx[cell * 32 + rl] = (unsigned char)x[(32 * mr + rl) * 256 + cell];
        }
        __syncthreads();
        if (tid >= 32) return;

        const int lane = tid;
        const int b = 32 * mr + lane;
        const float bo0 = bout[0], bo1 = bout[1];
        int* myz = g_zflags + 16 * mr;             // 2 m-groups x 8 z-flags
        float lp = 0.f;
        for (int t = 1; t <= T_STEPS; ++t) {
            if (lane < 16) {
                while (ld_acquire(myz + lane) < t) { }
            }
            __syncwarp();
            asm volatile("membar.gl;" ::: "memory");
            float z0 = bo0, z1 = bo1;
            const float2* zp = g_zpart + (t & (ZDEPTH - 1)) * (NTn * 4 * B_) + b;
#pragma unroll
            for (int i = 0; i < 32; ++i) {
                float2 v = ldg_cg_f2(zp + i * B_);
                z0 += v.x; z1 += v.y;
            }
            int s = t - 1, r = s >> 4, p = s & 15;
            int c = (r & 1) ? (15 - p) : p;
            int spin = sx[(r * 16 + c) * 32 + lane];
            float mz = fmaxf(z0, z1);
            float lse = mz + logf(expf(z0 - mz) + expf(z1 - mz));
            lp += (spin ? z1 : z0) - lse;
            __syncwarp();
            if (lane == 0) st_release(&g_rflags[mr], t);
        }
        out[b] = lp;
        return;
    }

    // ---------------- compute CTA ----------------
    const int m = bx >> 3, n = bx & 7;           // 16-row group, 64-col tile
    const int w = tid >> 5, lane = tid & 31;
    const int wc = w & 3;                        // column group (16 cols); pair (w, w+4)
    const int n0 = n * N_TILE;
    const int q = lane >> 2, tg = lane & 3;

    // K-split: warp pair (wc, wc+4) shares cols, splits the 32 kk chunks.
    // cv split asymmetric so warp0's flag poll overlaps cv work.
    int cvLo, cvN;
    if (w == 0)      { cvLo = 0;  cvN = 8;  }
    else if (w == 4) { cvLo = 8;  cvN = 24; }
    else if (w < 4)  { cvLo = 0;  cvN = 16; }
    else             { cvLo = 16; cvN = 16; }
    const int frLo = (w < 4) ? 0 : 16;           // fresh split: 16 kk each

    const unsigned sCV_s = (unsigned)__cvta_generic_to_shared(smem + SM_CV);
    const unsigned sFR_s = (unsigned)__cvta_generic_to_shared(smem + SM_FR);
    const unsigned wt_s  = (unsigned)__cvta_generic_to_shared(Wt);
    const unsigned aOff  = ((lane >> 3) << 7) + ((lane & 7) << 4);
    const unsigned brow  = 16 * wc + 8 * (lane >> 4) + (lane & 7);
    const unsigned bOff  = wt_s + brow * (WT_STRIDE * 2) + (((lane >> 3) & 1) << 4);

    // resident weight slice: Wt[j][k] = W[k][n0+j]
    for (int i = tid; i < N_TILE * 1024; i += THREADS) {
        int j = i >> 10, k = i & 1023;
        float wv = (k < U_) ? Wch[k * U_ + n0 + j] : Wcv[(k - U_) * U_ + n0 + j];
        Wt[j * WT_STRIDE + k] = __float2half_rn(wv);
    }
    if (tid < 64) {
        sWih[tid]       = Wih[n0 + tid];
        sWih[64 + tid]  = Wih[U_ + n0 + tid];
        sWiv[tid]       = Wiv[n0 + tid];
        sWiv[64 + tid]  = Wiv[U_ + n0 + tid];
        sBch[tid]       = bch[n0 + tid];
        sWo0[tid]       = Wout[(n0 + tid) * 2 + 0];
        sWo1[tid]       = Wout[(n0 + tid) * 2 + 1];
    }
    for (int i = tid; i < 4096; i += THREADS) {  // spins for this CTA's 16 rows
        int rl = i & 15, cell = i >> 4;
        sx[cell * 16 + rl] = (unsigned char)x[(16 * m + rl) * 256 + cell];
    }
    __syncthreads();

    int* myflags = g_flags + m * 8;

#pragma unroll 1
    for (int t = 1; t <= T_STEPS; ++t) {
        const int s = t - 1;
        const int r = s >> 4, p = s & 15;
        const int c  = (r & 1) ? (15 - p) : p;
        const int cp = (r & 1) ? (c + 1) : (c - 1);
        const bool has_h = (p > 0), has_v = (r > 0);
        const bool oldcv = has_h && has_v;       // old-cv GEMM active this step

        // S0: cv prefetch (issued by warps 4-7 at end of t-1) landed + visible
        cp_wait<0>();
        __syncthreads();

        // warp0 polls while warps 1-7 run their cv shares (warp4 carries 24 kk)
        if (w == 0 && t > 1) {
            if (lane < 8) {
                while (ld_acquire(myflags + lane) < t - 1) { }
            }
            if (lane == 8 && t > ZDEPTH) {
                while (ld_acquire(&g_rflags[m >> 1]) < t - ZDEPTH) { }
            }
        }

        float acc[2][4];
#pragma unroll
        for (int f = 0; f < 2; ++f)
            acc[f][0] = acc[f][1] = acc[f][2] = acc[f][3] = 0.f;

        if (oldcv)
            gemm_r(sCV_s + cvLo * 512 + aOff, bOff + 1024 + cvLo * 32, cvN, acc);

        __syncthreads();                         // S1: deps acquired + sCV reads done

        if (t > 1) {
            const unsigned* fsrc = has_h ? (pslab(r & 1, cp) + (m << 12))
                                         : (pslab((r - 1) & 1, c) + (m << 12));
#pragma unroll
            for (int i = 0; i < 4; ++i)
                cp_async16(sFR_s + tid * 16 + i * 4096, fsrc + tid * 4 + i * 1024);
            cp_commit();
            cp_wait<0>();
        }
        __syncthreads();                         // S2: fresh tile staged

        if (t > 1)
            gemm_r(sFR_s + frLo * 512 + aOff,
                   (has_h ? bOff : bOff + 1024) + frLo * 32, 16, acc);

        {   // publish this warp's K-partials
            float4* pp = (float4*)(sPart + (w * 32 + lane) * 8);
            pp[0] = make_float4(acc[0][0], acc[0][1], acc[0][2], acc[0][3]);
            pp[1] = make_float4(acc[1][0], acc[1][1], acc[1][2], acc[1][3]);
        }
        __syncthreads();                         // S3: partials visible

        if (w < 4) {
            // ---- epilogue (4 warps, 16 cols each): sum K-halves, finish cell
            const float4* pa = (const float4*)(sPart + (w * 32 + lane) * 8);
            const float4* pb = (const float4*)(sPart + ((w + 4) * 32 + lane) * 8);
            float4 a0 = pa[0], a1 = pa[1], b0v = pb[0], b1v = pb[1];
            acc[0][0] = a0.x + b0v.x; acc[0][1] = a0.y + b0v.y;
            acc[0][2] = a0.z + b0v.z; acc[0][3] = a0.w + b0v.w;
            acc[1][0] = a1.x + b1v.x; acc[1][1] = a1.y + b1v.y;
            acc[1][2] = a1.z + b1v.z; acc[1][3] = a1.w + b1v.w;

            int sLa = 0, sLb = 0, sUa = 0, sUb = 0;
            if (has_h) {
                sLa = sx[(r * 16 + cp) * 16 + q];
                sLb = sx[(r * 16 + cp) * 16 + q + 8];
            }
            if (has_v) {
                sUa = sx[((r - 1) * 16 + c) * 16 + q];
                sUb = sx[((r - 1) * 16 + c) * 16 + q + 8];
            }

            float z0a = 0.f, z1a = 0.f, z0b = 0.f, z1b = 0.f;
            unsigned* Pout = pslab(r & 1, c) + (m << 12) + ((4 * n + w) << 7) + lane;
#pragma unroll
            for (int f = 0; f < 2; ++f) {
                int u0 = 16 * w + 8 * f + 2 * tg;
                float v0 = acc[f][0] + sBch[u0];
                float v1 = acc[f][1] + sBch[u0 + 1];
                float v2 = acc[f][2] + sBch[u0];
                float v3 = acc[f][3] + sBch[u0 + 1];
                if (has_h) {
                    v0 += sWih[sLa * 64 + u0]; v1 += sWih[sLa * 64 + u0 + 1];
                    v2 += sWih[sLb * 64 + u0]; v3 += sWih[sLb * 64 + u0 + 1];
                }
                if (has_v) {
                    v0 += sWiv[sUa * 64 + u0]; v1 += sWiv[sUa * 64 + u0 + 1];
                    v2 += sWiv[sUb * 64 + u0]; v3 += sWiv[sUb * 64 + u0 + 1];
                }
                v0 = elu1(v0); v1 = elu1(v1); v2 = elu1(v2); v3 = elu1(v3);

                z0a += v0 * sWo0[u0] + v1 * sWo0[u0 + 1];
                z1a += v0 * sWo1[u0] + v1 * sWo1[u0 + 1];
                z0b += v2 * sWo0[u0] + v3 * sWo0[u0 + 1];
                z1b += v2 * sWo1[u0] + v3 * sWo1[u0 + 1];

                Pout[(2 * f) * 32]     = packh2(v0, v1);
                Pout[(2 * f + 1) * 32] = packh2(v2, v3);
            }

            // EARLY release: peers only need the Pout stores
            bar_sync(1, 128);
            if (tid == 0) st_release(&g_flags[bx], t);

            // z tail (reducer consumers only) — off the peer-critical path
            z0a += __shfl_xor_sync(0xffffffffu, z0a, 1);
            z0a += __shfl_xor_sync(0xffffffffu, z0a, 2);
            z1a += __shfl_xor_sync(0xffffffffu, z1a, 1);
            z1a += __shfl_xor_sync(0xffffffffu, z1a, 2);
            z0b += __shfl_xor_sync(0xffffffffu, z0b, 1);
            z0b += __shfl_xor_sync(0xffffffffu, z0b, 2);
            z1b += __shfl_xor_sync(0xffffffffu, z1b, 1);
            z1b += __shfl_xor_sync(0xffffffffu, z1b, 2);
            if (tg == 0) {
                float2* zp = g_zpart + (((t & (ZDEPTH - 1)) * NTn + n) * 4 + w) * B_;
                int bA = 16 * m + q;
                zp[bA]     = make_float2(z0a, z1a);
                zp[bA + 8] = make_float2(z0b, z1b);
            }
            bar_sync(1, 128);
            if (tid == 0) st_release(&g_zflags[bx], t);
        } else if (t < T_STEPS) {
            // ---- warps 4-7: prefetch next step's old-cv tile (overlaps epilogue)
            int r2 = t >> 4, p2 = t & 15;
            if (p2 >= 1 && r2 >= 1) {
                int c2 = (r2 & 1) ? (15 - p2) : p2;
                const unsigned* src = pslab((r2 - 1) & 1, c2) + (m << 12);
                int tl = tid - 128;
#pragma unroll
                for (int i = 0; i < 8; ++i)
                    cp_async16(sCV_s + tl * 16 + i * 2048, src + tl * 4 + i * 512);
            }
            cp_commit();
        }
    }
}

extern "C" void kernel_launch(void* const* d_in, const int* in_sizes, int n_in,
                              void* d_out, int out_size)
{
    (void)in_sizes; (void)n_in; (void)out_size;
    const int*   x    = (const int*)  d_in[0];
    const float* Wih  = (const float*)d_in[1];
    const float* Wiv  = (const float*)d_in[2];
    const float* Wch  = (const float*)d_in[3];
    const float* bch  = (const float*)d_in[4];
    const float* Wcv  = (const float*)d_in[5];
    const float* Wout = (const float*)d_in[6];
    const float* bout = (const float*)d_in[7];
    float* out = (float*)d_out;

    cudaFuncSetAttribute(rnn2d_main_kernel,
                         cudaFuncAttributeMaxDynamicSharedMemorySize, SM_TOTAL);

    rnn2d_init_kernel<<<1, 128>>>();
    rnn2d_main_kernel<<<NCOMP + NRED, THREADS, SM_TOTAL>>>(
        x, Wih, Wiv, Wch, bch, Wcv, Wout, bout, out);
}